// round 9
// baseline (speedup 1.0000x reference)
#include <cuda_runtime.h>
#include <cuda_bf16.h>

// Balloon-Windkessel BOLD, 1000 Euler steps — parallel-in-time, v3.
// TWO scan passes total:
//   Pass 1: Newton sweep for v from an analytically lag-corrected warm start
//           vk = f^a - mtt*a^2*f^(2a-2)*s   (s_t = (2/sqrt3) r^t sin(t*th),
//           closed form like f_t). Warm-start err ~1e-3 -> post-sweep ~1e-6.
//   Pass 2: FUSED double-wide affine scan: final Newton sweep for v (exact)
//           + q-scan, sharing one u = v_t^2.125 MUFU pair.
// 4 __syncthreads total. Thread t owns step t; block = 1024 threads.

#define N_STEPS 1000
#define NT      1024
#define DT      0.01f
#define RHO     0.34f
#define ALPHA   0.32f

#define LOG2R   (-0.0071769220f)   // log2(sqrt(1 - h + h^2)), h = 0.01
#define THETA   (0.0087035531f)    // atan2(sqrt(3)/2*h, 1 - h/2)
#define INVSQ3  (0.57735026919f)
#define TWOSQ3  (1.15470053838f)   // 2/sqrt(3)
#define L66     (-0.5994621118f)   // log2(0.66)
#define A2      (ALPHA*ALPHA)      // 0.1024
#define PEXP    (2.0f*ALPHA-2.0f)  // -1.36

#define YC   0.0972f
#define YK1  0.0476f
#define YK2  0.04f
#define YK3  0.0096f

__device__ __forceinline__ float ex2a(float x){ float r; asm("ex2.approx.f32 %0,%1;":"=f"(r):"f"(x)); return r; }
__device__ __forceinline__ float lg2a(float x){ float r; asm("lg2.approx.f32 %0,%1;":"=f"(r):"f"(x)); return r; }
__device__ __forceinline__ float sina(float x){ float r; asm("sin.approx.f32 %0,%1;":"=f"(r):"f"(x)); return r; }
__device__ __forceinline__ float cosa(float x){ float r; asm("cos.approx.f32 %0,%1;":"=f"(r):"f"(x)); return r; }
__device__ __forceinline__ float rcpa(float x){ float r; asm("rcp.approx.f32 %0,%1;":"=f"(r):"f"(x)); return r; }

// Pass 1: single affine scan, returns inclusive (A,B) and exclusive (exA,exB).
__device__ __forceinline__ void scan1(float& A, float& B, float& exA, float& exB,
                                      int lane, int warp, float* sA, float* sB) {
    #pragma unroll
    for (int d = 1; d < 32; d <<= 1) {
        float pA = __shfl_up_sync(0xffffffffu, A, d);
        float pB = __shfl_up_sync(0xffffffffu, B, d);
        if (lane >= d) { B = fmaf(A, pB, B); A = A * pA; }
    }
    if (lane == 31) { sA[warp] = A; sB[warp] = B; }
    __syncthreads();
    if (warp == 0) {
        float wA = sA[lane], wB = sB[lane];
        #pragma unroll
        for (int d = 1; d < 32; d <<= 1) {
            float pA = __shfl_up_sync(0xffffffffu, wA, d);
            float pB = __shfl_up_sync(0xffffffffu, wB, d);
            if (lane >= d) { wB = fmaf(wA, pB, wB); wA = wA * pA; }
        }
        sA[lane] = wA; sB[lane] = wB;
    }
    __syncthreads();
    float pA = 1.0f, pB = 0.0f;
    if (warp > 0) { pA = sA[warp - 1]; pB = sB[warp - 1]; }
    B = fmaf(A, pB, B);
    A = A * pA;
    exA = __shfl_up_sync(0xffffffffu, A, 1);
    exB = __shfl_up_sync(0xffffffffu, B, 1);
    if (lane == 0) { exA = pA; exB = pB; }
}

// Pass 2: dual affine scan (two independent maps), inclusive only.
__device__ __forceinline__ void scan2(float& A, float& B, float& C, float& D,
                                      int lane, int warp,
                                      float* sA, float* sB, float* sC, float* sD) {
    #pragma unroll
    for (int d = 1; d < 32; d <<= 1) {
        float pA = __shfl_up_sync(0xffffffffu, A, d);
        float pB = __shfl_up_sync(0xffffffffu, B, d);
        float pC = __shfl_up_sync(0xffffffffu, C, d);
        float pD = __shfl_up_sync(0xffffffffu, D, d);
        if (lane >= d) {
            B = fmaf(A, pB, B); A = A * pA;
            D = fmaf(C, pD, D); C = C * pC;
        }
    }
    if (lane == 31) { sA[warp] = A; sB[warp] = B; sC[warp] = C; sD[warp] = D; }
    __syncthreads();
    if (warp == 0) {
        float wA = sA[lane], wB = sB[lane], wC = sC[lane], wD = sD[lane];
        #pragma unroll
        for (int d = 1; d < 32; d <<= 1) {
            float pA = __shfl_up_sync(0xffffffffu, wA, d);
            float pB = __shfl_up_sync(0xffffffffu, wB, d);
            float pC = __shfl_up_sync(0xffffffffu, wC, d);
            float pD = __shfl_up_sync(0xffffffffu, wD, d);
            if (lane >= d) {
                wB = fmaf(wA, pB, wB); wA = wA * pA;
                wD = fmaf(wC, pD, wD); wC = wC * pC;
            }
        }
        sA[lane] = wA; sB[lane] = wB; sC[lane] = wC; sD[lane] = wD;
    }
    __syncthreads();
    if (warp > 0) {
        float pA = sA[warp - 1], pB = sB[warp - 1];
        float pC = sC[warp - 1], pD = sD[warp - 1];
        B = fmaf(A, pB, B); A = A * pA;
        D = fmaf(C, pD, D); C = C * pC;
    }
}

__global__ void __launch_bounds__(NT, 1)
bold_pits_kernel(const float* __restrict__ mtt_ptr, float* __restrict__ y_out) {
    __shared__ float s0[32], s1[32], s2[32], s3[32], s4[32], s5[32];

    const int t    = threadIdx.x;
    const int lane = t & 31;
    const int warp = t >> 5;
    const bool active = (t < N_STEPS);

    const float mtt = mtt_ptr[0];
    const float dtm = DT / mtt;

    // ---- elementwise: f, s, E, coefficients, lag-corrected warm start -----
    float a_t = 0.0f, g_t = 0.0f, vk = 1.0f;
    if (active) {
        float tf  = (float)t;
        float rp  = ex2a(LOG2R * tf);                  // r^t
        float ang = THETA * tf;
        float sn  = sina(ang);
        float f   = 2.0f - rp * fmaf(sn, INVSQ3, cosa(ang));
        float s_t = TWOSQ3 * rp * sn;                  // closed-form s_t
        float E   = 1.0f - ex2a(L66 * rcpa(f));
        a_t = dtm * f;
        g_t = (dtm / RHO) * f * E;
        float lgf = lg2a(f);
        float fa  = ex2a(ALPHA * lgf);                 // f^alpha
        float fp  = ex2a(PEXP * lgf);                  // f^(2a-2)
        vk = fmaf(-mtt * A2 * s_t, fp, fa);            // lag-corrected guess of v_t
    }

    // ---- Pass 1: Newton sweep for v ---------------------------------------
    float A = 1.0f, B = 0.0f, exA, exB;
    if (active) {
        float u = ex2a(2.125f * lg2a(vk));             // vk^2.125
        A = fmaf(-3.125f * dtm, u, 1.0f);
        B = fmaf(2.125f * dtm, vk * u, a_t);
    }
    scan1(A, B, exA, exB, lane, warp, s0, s1);
    vk = exA + exB;                                    // refined v_t (~1e-6)

    // ---- Pass 2: fused final Newton sweep (v) + q-scan --------------------
    float Av = 1.0f, Bv = 0.0f, Aq = 1.0f, Bq = 0.0f;
    if (active) {
        float u = ex2a(2.125f * lg2a(vk));             // v_t^2.125 (shared)
        Av = fmaf(-3.125f * dtm, u, 1.0f);
        Bv = fmaf(2.125f * dtm, vk * u, a_t);
        Aq = fmaf(-dtm, u, 1.0f);
        Bq = g_t;
    }
    scan2(Av, Bv, Aq, Bq, lane, warp, s2, s3, s4, s5);
    float v_next = Av + Bv;                            // v_{t+1} (v_0 = 1)
    float q_next = Aq + Bq;                            // q_{t+1} (q_0 = 1)

    // ---- BOLD readout ------------------------------------------------------
    if (active) {
        float yt = fmaf(-YK1, q_next, YC);
        yt = fmaf(-YK3, v_next, yt);
        yt = fmaf(-YK2, q_next * rcpa(v_next), yt);
        y_out[t] = yt;
    }
}

extern "C" void kernel_launch(void* const* d_in, const int* in_sizes, int n_in,
                              void* d_out, int out_size) {
    const float* mtt = (const float*)d_in[0];
    float* y = (float*)d_out;
    bold_pits_kernel<<<1, NT>>>(mtt, y);
}